// round 10
// baseline (speedup 1.0000x reference)
#include <cuda_runtime.h>
#include <cstdint>

// HighOrderFactorizationMachineModel: BATCH=16384, F=20, EMBED_DIM=16, ORDER=3.
// emb row = 32 floats: [0:16) order-2 dims, [16:32) order-3 dims.
// Closed forms via power sums: e2=(p1^2-p2)/2, e3=(p1^3-3p1p2+2p3)/6.
//
// R10: emb gathers via cp.async.bulk (UBLKCP, async-proxy engine) instead of
// LDG. Little's-law on six rounds of invariant results shows ~66 outstanding
// lines/SM -- an L1tex miss-pool cap that no LDG-side structure can beat.
// Bulk-engine requests are tracked in the async engine (deep queue, no MSHR),
// raising chip-level memory concurrency. 20 x 128B bulk copies per warp into
// smem, one warp-private mbarrier, lin gathers overlap as plain LDG.

#define FM_BATCH 16384
#define FM_F 20
#define FM_FIELD_DIM 50000
#define WPB 8   // warps per block

__global__ __launch_bounds__(32 * WPB)
void fm_ho_kernel(const int* __restrict__ x,
                  const float* __restrict__ emb,
                  const float* __restrict__ lin,
                  const float* __restrict__ bias,
                  float* __restrict__ out)
{
    __shared__ __align__(16) float buf[WPB][FM_F * 32];          // 2560 B/warp
    __shared__ __align__(8)  unsigned long long mbar[WPB];

    const int wid  = threadIdx.x >> 5;
    const int lane = threadIdx.x & 31;
    const int s    = blockIdx.x * WPB + wid;   // one sample per warp

    uint32_t mbar_a, buf_a;
    asm("{ .reg .u64 t; cvta.to.shared.u64 t, %1; cvt.u32.u64 %0, t; }"
        : "=r"(mbar_a) : "l"(&mbar[wid]));
    asm("{ .reg .u64 t; cvta.to.shared.u64 t, %1; cvt.u32.u64 %0, t; }"
        : "=r"(buf_a) : "l"(&buf[wid][0]));

    // Index row: 20 ints = 80B, 16B-aligned -> 5x int4 broadcast loads.
    int idx[FM_F];
    {
        const int4* xr = (const int4*)(x + s * FM_F);
        #pragma unroll
        for (int q = 0; q < FM_F / 4; q++) {
            const int4 t = __ldg(&xr[q]);
            idx[4 * q + 0] = t.x + (4 * q + 0) * FM_FIELD_DIM;
            idx[4 * q + 1] = t.y + (4 * q + 1) * FM_FIELD_DIM;
            idx[4 * q + 2] = t.z + (4 * q + 2) * FM_FIELD_DIM;
            idx[4 * q + 3] = t.w + (4 * q + 3) * FM_FIELD_DIM;
        }
    }

    // Warp-private mbarrier: init + async-proxy fence + expect_tx by lane 0.
    if (lane == 0) {
        asm volatile("mbarrier.init.shared.b64 [%0], 1;" :: "r"(mbar_a) : "memory");
        asm volatile("fence.proxy.async.shared::cta;" ::: "memory");
        asm volatile("mbarrier.arrive.expect_tx.shared.b64 _, [%0], %1;"
                     :: "r"(mbar_a), "r"(FM_F * 128) : "memory");
    }
    __syncwarp();

    // Lanes 0..19: one 128B bulk copy each (row is 128B-aligned in gmem,
    // dst 128B-strided in smem). Handled by the async engine, not L1tex.
    if (lane < FM_F) {
        const float* src = emb + (long)idx[lane] * 32;
        const uint32_t dst = buf_a + lane * 128;
        asm volatile(
            "cp.async.bulk.shared::cta.global.mbarrier::complete_tx::bytes "
            "[%0], [%1], 128, [%2];"
            :: "r"(dst), "l"(src), "r"(mbar_a) : "memory");
    }

    // Overlap: linear-term gather (lanes 0..19) while bulk copies fly.
    float linv = 0.0f;
    if (lane < FM_F)
        linv = __ldg(&lin[idx[lane]]);

    // Wait for all 2560 bytes.
    {
        uint32_t done;
        asm volatile(
            "{\n\t.reg .pred p;\n\t"
            "mbarrier.try_wait.parity.acquire.cta.shared::cta.b64 p, [%1], 0;\n\t"
            "selp.b32 %0, 1, 0, p;\n\t}"
            : "=r"(done) : "r"(mbar_a) : "memory");
        if (!done) {
            asm volatile(
                "{\n\t.reg .pred P1;\n\t"
                "WL_%=:\n\t"
                "mbarrier.try_wait.parity.acquire.cta.shared::cta.b64 P1, [%0], 0, 0x989680;\n\t"
                "@P1 bra.uni WD_%=;\n\t"
                "bra.uni WL_%=;\n\t"
                "WD_%=:\n\t}"
                :: "r"(mbar_a) : "memory");
        }
    }

    // Power sums: lane l reads element l of each row (stride 128B -> bank l,
    // conflict-free).
    float p1 = 0.0f, p2 = 0.0f, p3 = 0.0f;
    #pragma unroll
    for (int f = 0; f < FM_F; f++) {
        const float w = buf[wid][f * 32 + lane];
        const float w2 = w * w;
        p1 += w;
        p2 += w2;
        p3 += w2 * w;
    }

    // Lanes 0..15: order-2 dims. Lanes 16..31: order-3 dims.
    float term;
    if (lane < 16) {
        term = 0.5f * (p1 * p1 - p2);
    } else {
        term = (p1 * p1 * p1 - 3.0f * p1 * p2 + 2.0f * p3) * (1.0f / 6.0f);
    }
    term += linv;   // lanes 0..19 contribute linear part, others add 0

    // Warp-wide sum.
    #pragma unroll
    for (int o = 16; o > 0; o >>= 1)
        term += __shfl_xor_sync(0xffffffffu, term, o);

    if (lane == 0)
        out[s] = term + __ldg(&bias[0]);
}

extern "C" void kernel_launch(void* const* d_in, const int* in_sizes, int n_in,
                              void* d_out, int out_size)
{
    const int*   x    = (const int*)d_in[0];
    const float* emb  = (const float*)d_in[1];
    const float* lin  = (const float*)d_in[2];
    const float* bias = (const float*)d_in[3];
    float*       out  = (float*)d_out;

    // 16384 samples, 1 warp each, 8 warps/block -> 2048 blocks.
    const int threads = 32 * WPB;
    const int blocks  = FM_BATCH / WPB;
    fm_ho_kernel<<<blocks, threads>>>(x, emb, lin, bias, out);
}

// round 11
// speedup vs baseline: 1.1355x; 1.1355x over previous
#include <cuda_runtime.h>
#include <cstdint>

// HighOrderFactorizationMachineModel: BATCH=16384, F=20 fields (dim 50000 each),
// EMBED_DIM=16, ORDER=3. emb_table row = 32 floats: [0:16) order-2 dims,
// [16:32) order-3 dims. Closed forms via power sums (Newton identities):
//   e2 = (p1^2 - p2)/2
//   e3 = (p1^3 - 3 p1 p2 + 2 p3)/6
// so the O(F^2 D) ANOVA DP collapses to 3 accumulators per dim.
//
// FINAL FORM (R11). Ten rounds established this problem sits at the
// random-gather roofline:
//   cold  = 41 MB compulsory unique lines @ ~3.3 TB/s random-HBM ceiling
//   warm  = ~655k miss-requests x ~250cyc L2 latency / ~9.8k-line chip
//           concurrency cap (~66 outstanding lines per SM, L1tex pool)
// Structure-invariant across MLP 4..20, occ 39..109%, LDG.32/.128; all
// alternative paths (cp.async.cg, cache hints, bulk-async) regressed.
// One warp per sample, lane l owns row element l -> one coalesced 128B line
// per gather. Only remaining free win applied here: emb gathers issue BEFORE
// the divergent 20-wavefront lin gather (L1tex completion follows issue
// order; keep line fills ahead of scattered sectors in the queue).

#define FM_BATCH 16384
#define FM_F 20
#define FM_FIELD_DIM 50000

__global__ __launch_bounds__(256)
void fm_ho_kernel(const int* __restrict__ x,
                  const float* __restrict__ emb,
                  const float* __restrict__ lin,
                  const float* __restrict__ bias,
                  float* __restrict__ out)
{
    const int warp = (blockIdx.x * blockDim.x + threadIdx.x) >> 5;
    const int lane = threadIdx.x & 31;
    const int s = warp;

    // Index row: 20 ints = 80 B, 16B-aligned -> 5x int4 broadcast loads.
    int idx[FM_F];
    {
        const int4* xr = (const int4*)(x + s * FM_F);
        #pragma unroll
        for (int q = 0; q < FM_F / 4; q++) {
            const int4 t = __ldg(&xr[q]);
            idx[4 * q + 0] = t.x + (4 * q + 0) * FM_FIELD_DIM;
            idx[4 * q + 1] = t.y + (4 * q + 1) * FM_FIELD_DIM;
            idx[4 * q + 2] = t.z + (4 * q + 2) * FM_FIELD_DIM;
            idx[4 * q + 3] = t.w + (4 * q + 3) * FM_FIELD_DIM;
        }
    }

    // 20 independent emb gathers FIRST (each one fully-coalesced 128B line).
    float v[FM_F];
    #pragma unroll
    for (int f = 0; f < FM_F; f++)
        v[f] = __ldg(&emb[(long)idx[f] * 32 + lane]);

    // Divergent lin gather (20 scattered sectors) issued after the line fills.
    float linv = 0.0f;
    if (lane < FM_F)
        linv = __ldg(&lin[idx[lane]]);

    // Power sums.
    float p1 = 0.0f, p2 = 0.0f, p3 = 0.0f;
    #pragma unroll
    for (int f = 0; f < FM_F; f++) {
        const float w = v[f];
        const float w2 = w * w;
        p1 += w;
        p2 += w2;
        p3 += w2 * w;
    }

    // Lanes 0..15: order-2 dims. Lanes 16..31: order-3 dims.
    float term;
    if (lane < 16) {
        term = 0.5f * (p1 * p1 - p2);
    } else {
        term = (p1 * p1 * p1 - 3.0f * p1 * p2 + 2.0f * p3) * (1.0f / 6.0f);
    }
    term += linv;   // lanes 0..19 contribute linear part, others add 0

    // Warp-wide sum.
    #pragma unroll
    for (int o = 16; o > 0; o >>= 1)
        term += __shfl_xor_sync(0xffffffffu, term, o);

    if (lane == 0)
        out[s] = term + __ldg(&bias[0]);
}

extern "C" void kernel_launch(void* const* d_in, const int* in_sizes, int n_in,
                              void* d_out, int out_size)
{
    const int*   x    = (const int*)d_in[0];
    const float* emb  = (const float*)d_in[1];
    const float* lin  = (const float*)d_in[2];
    const float* bias = (const float*)d_in[3];
    float*       out  = (float*)d_out;

    // 16384 samples, 1 warp each, 8 warps/block -> 2048 blocks.
    const int threads = 256;
    const int blocks  = (FM_BATCH * 32) / threads;
    fm_ho_kernel<<<blocks, threads>>>(x, emb, lin, bias, out);
}

// round 12
// speedup vs baseline: 1.5761x; 1.3881x over previous
#include <cuda_runtime.h>
#include <cstdint>

// HighOrderFactorizationMachineModel: BATCH=16384, F=20 fields (dim 50000 each),
// EMBED_DIM=16, ORDER=3. emb_table row = 32 floats: [0:16) order-2 dims,
// [16:32) order-3 dims. Closed forms via power sums (Newton identities):
//   e2 = (p1^2 - p2)/2
//   e3 = (p1^3 - 3 p1 p2 + 2 p3)/6
// collapsing the O(F^2 D) ANOVA DP to 3 accumulators per dim.
//
// FINAL (R12 = R1 verbatim, the twice-validated 10.7us optimum).
// Eleven rounds of evidence: this problem is pinned at the random-gather
// roofline (cold: 41MB compulsory lines @ ~3.3TB/s random-HBM; warm: ~655k
// miss-requests under the ~66-outstanding-lines/SM L1tex cap). Structure
// variations (MLP 4..20, occ 39..109%, LDG.32/.128) were invariant; all
// alternative load paths (cp.async.cg, L2 cache hints both polarities,
// cp.async.bulk) and the emb-before-lin reorder regressed 40-60%.
// Critical detail: the divergent lin gather must issue EARLY so its 20
// scattered-sector wavefronts overlap the emb line fills instead of queuing
// behind the next warps' batches (R11 proved this costs 40% if violated).

#define FM_BATCH 16384
#define FM_F 20
#define FM_FIELD_DIM 50000

__global__ __launch_bounds__(256)
void fm_ho_kernel(const int* __restrict__ x,
                  const float* __restrict__ emb,
                  const float* __restrict__ lin,
                  const float* __restrict__ bias,
                  float* __restrict__ out)
{
    const int warp = (blockIdx.x * blockDim.x + threadIdx.x) >> 5;
    const int lane = threadIdx.x & 31;
    if (warp >= FM_BATCH) return;

    // Lane f holds the global table index for field f (offsets = f * 50000).
    int gidx = 0;
    float linv = 0.0f;
    if (lane < FM_F) {
        gidx = x[warp * FM_F + lane] + lane * FM_FIELD_DIM;
        linv = __ldg(&lin[gidx]);
    }

    float p1 = 0.0f, p2 = 0.0f, p3 = 0.0f;

    #pragma unroll
    for (int f = 0; f < FM_F; f++) {
        const int idx = __shfl_sync(0xffffffffu, gidx, f);
        const float v = __ldg(&emb[(long)idx * 32 + lane]);
        const float v2 = v * v;
        p1 += v;
        p2 += v2;
        p3 += v2 * v;
    }

    // Lanes 0..15: order-2 dims. Lanes 16..31: order-3 dims.
    float term;
    if (lane < 16) {
        term = 0.5f * (p1 * p1 - p2);
    } else {
        term = (p1 * p1 * p1 - 3.0f * p1 * p2 + 2.0f * p3) * (1.0f / 6.0f);
    }
    term += linv;  // lanes 0..19 contribute linear part, others added 0

    // Warp-wide sum.
    #pragma unroll
    for (int o = 16; o > 0; o >>= 1)
        term += __shfl_xor_sync(0xffffffffu, term, o);

    if (lane == 0)
        out[warp] = term + __ldg(&bias[0]);
}

extern "C" void kernel_launch(void* const* d_in, const int* in_sizes, int n_in,
                              void* d_out, int out_size)
{
    const int*   x    = (const int*)d_in[0];
    const float* emb  = (const float*)d_in[1];
    const float* lin  = (const float*)d_in[2];
    const float* bias = (const float*)d_in[3];
    float*       out  = (float*)d_out;

    // 16384 samples, 1 warp each, 8 warps/block -> 2048 blocks.
    const int threads = 256;
    const int blocks  = (FM_BATCH * 32) / threads;
    fm_ho_kernel<<<blocks, threads>>>(x, emb, lin, bias, out);
}